// round 1
// baseline (speedup 1.0000x reference)
#include <cuda_runtime.h>
#include <cstdint>

#define WS      8
#define SHIFT   4
#define NDIM    256
#define DSTATE  8
#define DCONV   4
#define DINNER  256
#define DTRANK  16
#define LTOK    64          // WS*WS tokens per window
#define NWIN    1024        // 4 * 16 * 16 windows
#define LDA     264         // padded row stride (floats) for 64x256 smem buffers

// -------- transposed weight scratch (device globals; no allocation) --------
__device__ float g_WinT[256 * 512];   // [d][e]  e in [0,512)
__device__ float g_WoutT[256 * 256];  // [d][e]
__device__ float g_WxT[256 * 32];     // [d][e]  e in [0,32)
__device__ float g_WdtT[16 * 256];    // [r][d]

__global__ void prep_transpose_kernel(const float* __restrict__ W_in,
                                      const float* __restrict__ W_xproj,
                                      const float* __restrict__ W_dt,
                                      const float* __restrict__ W_out) {
    int idx = blockIdx.x * blockDim.x + threadIdx.x;
    int stride = gridDim.x * blockDim.x;
    for (int i = idx; i < 512 * 256; i += stride) {
        int e = i / 256, d = i % 256;
        g_WinT[d * 512 + e] = W_in[i];
    }
    for (int i = idx; i < 256 * 256; i += stride) {
        int e = i / 256, d = i % 256;
        g_WoutT[d * 256 + e] = W_out[i];
    }
    for (int i = idx; i < 32 * 256; i += stride) {
        int e = i / 256, d = i % 256;
        g_WxT[d * 32 + e] = W_xproj[i];
    }
    for (int i = idx; i < 256 * 16; i += stride) {
        int d = i / 16, r = i % 16;
        g_WdtT[r * 256 + d] = W_dt[i];
    }
}

// -------- packed f32x2 helpers --------
__device__ __forceinline__ unsigned long long pack2(float lo, float hi) {
    unsigned long long r;
    asm("mov.b64 %0, {%1, %2};" : "=l"(r) : "f"(lo), "f"(hi));
    return r;
}
__device__ __forceinline__ void unpack2(unsigned long long v, float& lo, float& hi) {
    asm("mov.b64 {%0, %1}, %2;" : "=f"(lo), "=f"(hi) : "l"(v));
}
__device__ __forceinline__ void fma2(unsigned long long& d, unsigned long long a,
                                     unsigned long long b) {
    asm("fma.rn.f32x2 %0, %1, %2, %0;" : "+l"(d) : "l"(a), "l"(b));
}

// 64x256 <- (64x256) @ WtT(256 x ldw)[:, ecol0:ecol0+256], smem-staged weight chunks.
// Thread (ty,tx) computes 8t x 8e tile via f32x2 pairs over t.
__device__ void gemm64x256(const float* __restrict__ Wt, int ldw, int ecol0,
                           const float* sIn, float* sOut, float* sW, int tid) {
    const int tx = tid & 31, ty = tid >> 5;
    const int tb = ty * 8;
    unsigned long long acc[4][8];
#pragma unroll
    for (int p = 0; p < 4; p++)
#pragma unroll
        for (int jj = 0; jj < 8; jj++) acc[p][jj] = 0ull;

    float pre[8];
#pragma unroll
    for (int i = 0; i < 8; i++) pre[i] = Wt[i * ldw + ecol0 + tid];

    for (int k0 = 0; k0 < 256; k0 += 8) {
        __syncthreads();  // previous chunk's readers done with sW
#pragma unroll
        for (int i = 0; i < 8; i++) sW[i * 256 + tid] = pre[i];
        __syncthreads();
        if (k0 + 8 < 256) {
#pragma unroll
            for (int i = 0; i < 8; i++) pre[i] = Wt[(k0 + 8 + i) * ldw + ecol0 + tid];
        }
#pragma unroll
        for (int j = 0; j < 8; j++) {
            unsigned long long a[4];
#pragma unroll
            for (int p = 0; p < 4; p++)
                a[p] = pack2(sIn[(tb + 2 * p) * LDA + k0 + j],
                             sIn[(tb + 2 * p + 1) * LDA + k0 + j]);
#pragma unroll
            for (int jj = 0; jj < 8; jj++) {
                float w = sW[j * 256 + tx + 32 * jj];
                unsigned long long b = pack2(w, w);
#pragma unroll
                for (int p = 0; p < 4; p++) fma2(acc[p][jj], a[p], b);
            }
        }
    }
#pragma unroll
    for (int p = 0; p < 4; p++)
#pragma unroll
        for (int jj = 0; jj < 8; jj++) {
            float lo, hi;
            unpack2(acc[p][jj], lo, hi);
            sOut[(tb + 2 * p) * LDA + tx + 32 * jj] = lo;
            sOut[(tb + 2 * p + 1) * LDA + tx + 32 * jj] = hi;
        }
}

__device__ __forceinline__ float silu_f(float v) {
    return v / (1.0f + __expf(-v));
}

// smem: sA(64xLDA) | sB(64xLDA) | sC(64xLDA) | sW(8x256) | sBC(64x32)
#define SMEM_FLOATS (3 * LTOK * LDA + 8 * 256 + LTOK * 32)
#define SMEM_BYTES (SMEM_FLOATS * 4)

__global__ __launch_bounds__(256, 1) void swin_mamba_kernel(
    const float* __restrict__ x, const float* __restrict__ ln_g,
    const float* __restrict__ ln_b, const float* __restrict__ conv_w,
    const float* __restrict__ conv_b, const float* __restrict__ b_dt,
    const float* __restrict__ A_log, const float* __restrict__ D_param,
    float* __restrict__ out) {
    extern __shared__ float smem[];
    float* sA = smem;                 // xn -> dt_full
    float* sB = sA + LTOK * LDA;      // raw x -> xc -> xs -> y
    float* sC = sB + LTOK * LDA;      // z -> final out tile
    float* sW = sC + LTOK * LDA;      // weight staging [8][256]
    float* sBC = sW + 8 * 256;        // x_dbl [64][32]

    const int tid = threadIdx.x;
    const int n = blockIdx.x;
    const int b = n >> 8;
    const int rem = n & 255;
    const int wy = rem >> 4;
    const int wx = rem & 15;

    // ---- phase 0: gather rolled window into sB [t][c] (stride LDA) ----
#pragma unroll 4
    for (int i = 0; i < 64; i++) {
        int idx = tid + 256 * i;
        int ix = idx & 7;
        int c = (idx >> 3) & 255;
        int iy = idx >> 11;
        int t = iy * 8 + ix;
        int h = (wy * 8 + iy + SHIFT) & 127;
        int w = (wx * 8 + ix + SHIFT) & 127;
        sB[t * LDA + c] = x[(((b * 256 + c) << 7) + h) * 128 + w];
    }
    __syncthreads();

    // ---- phase 1: LayerNorm over c -> sA (warp per token) ----
    {
        const int wid = tid >> 5, lane = tid & 31;
        for (int t = wid; t < 64; t += 8) {
            float v[8], s = 0.f, s2 = 0.f;
#pragma unroll
            for (int j = 0; j < 8; j++) {
                v[j] = sB[t * LDA + lane + 32 * j];
                s += v[j];
                s2 += v[j] * v[j];
            }
#pragma unroll
            for (int o = 16; o > 0; o >>= 1) {
                s += __shfl_xor_sync(0xffffffffu, s, o);
                s2 += __shfl_xor_sync(0xffffffffu, s2, o);
            }
            float mu = s * (1.0f / 256.0f);
            float var = s2 * (1.0f / 256.0f) - mu * mu;
            float rstd = rsqrtf(var + 1e-5f);
#pragma unroll
            for (int j = 0; j < 8; j++) {
                int c = lane + 32 * j;
                sA[t * LDA + c] = (v[j] - mu) * rstd * ln_g[c] + ln_b[c];
            }
        }
    }
    __syncthreads();

    // ---- phase 2: xz = xn @ W_in^T : xc -> sB, z -> sC ----
    gemm64x256(g_WinT, 512, 0, sA, sB, sW, tid);
    __syncthreads();
    gemm64x256(g_WinT, 512, 256, sA, sC, sW, tid);
    __syncthreads();

    // ---- phase 3: depthwise causal conv + SiLU, in place in sB ----
    {
        const int d = tid;
        float w0 = conv_w[d * 4 + 0], w1 = conv_w[d * 4 + 1];
        float w2 = conv_w[d * 4 + 2], w3 = conv_w[d * 4 + 3];
        float cb = conv_b[d];
        float q0 = 0.f, q1 = 0.f, q2 = 0.f;
#pragma unroll 4
        for (int t = 0; t < 64; t++) {
            float q3 = sB[t * LDA + d];
            float v = cb + w0 * q0 + w1 * q1 + w2 * q2 + w3 * q3;
            sB[t * LDA + d] = silu_f(v);
            q0 = q1; q1 = q2; q2 = q3;
        }
    }
    __syncthreads();

    // ---- phase 4: x_dbl = xs @ W_xproj^T -> sBC [64][32] ----
    {
        const int tx = tid & 31, ty = tid >> 5, tb = ty * 8;
        float acc2[8];
#pragma unroll
        for (int i = 0; i < 8; i++) acc2[i] = 0.f;
#pragma unroll 4
        for (int k = 0; k < 256; k += 4) {
            float wv0 = g_WxT[(k + 0) * 32 + tx];
            float wv1 = g_WxT[(k + 1) * 32 + tx];
            float wv2 = g_WxT[(k + 2) * 32 + tx];
            float wv3 = g_WxT[(k + 3) * 32 + tx];
#pragma unroll
            for (int i = 0; i < 8; i++) {
                const float4 xv = *(const float4*)&sB[(tb + i) * LDA + k];
                acc2[i] = fmaf(xv.x, wv0, acc2[i]);
                acc2[i] = fmaf(xv.y, wv1, acc2[i]);
                acc2[i] = fmaf(xv.z, wv2, acc2[i]);
                acc2[i] = fmaf(xv.w, wv3, acc2[i]);
            }
        }
#pragma unroll
        for (int i = 0; i < 8; i++) sBC[(tb + i) * 32 + tx] = acc2[i];
    }
    __syncthreads();

    // ---- phase 5: dt_full = softplus(dt_raw @ W_dt^T + b_dt) -> sA ----
    {
        const int tx = tid & 31, ty = tid >> 5, tb = ty * 8;
        float acc3[8][8];
#pragma unroll
        for (int i = 0; i < 8; i++)
#pragma unroll
            for (int jj = 0; jj < 8; jj++) acc3[i][jj] = 0.f;
#pragma unroll
        for (int r = 0; r < 16; r++) {
            float wv[8];
#pragma unroll
            for (int jj = 0; jj < 8; jj++) wv[jj] = g_WdtT[r * 256 + tx + 32 * jj];
#pragma unroll
            for (int i = 0; i < 8; i++) {
                float dv = sBC[(tb + i) * 32 + r];
#pragma unroll
                for (int jj = 0; jj < 8; jj++)
                    acc3[i][jj] = fmaf(dv, wv[jj], acc3[i][jj]);
            }
        }
#pragma unroll
        for (int jj = 0; jj < 8; jj++) {
            float bb = b_dt[tx + 32 * jj];
#pragma unroll
            for (int i = 0; i < 8; i++) {
                float v = acc3[i][jj] + bb;
                v = (v > 20.0f) ? v : log1pf(__expf(v));
                sA[(tb + i) * LDA + tx + 32 * jj] = v;
            }
        }
    }
    __syncthreads();

    // ---- phase 6: selective scan + D skip + z gate, y -> sB ----
    {
        const int d = tid;
        float Aa[8];
#pragma unroll
        for (int s = 0; s < 8; s++) Aa[s] = -__expf(A_log[d * 8 + s]);
        float Dv = D_param[d];
        float h[8];
#pragma unroll
        for (int s = 0; s < 8; s++) h[s] = 0.f;
        for (int t = 0; t < 64; t++) {
            float dtv = sA[t * LDA + d];
            float xsv = sB[t * LDA + d];
            float zv = sC[t * LDA + d];
            float dbx = dtv * xsv;
            float y = 0.f;
#pragma unroll
            for (int s = 0; s < 8; s++) {
                float Bv = sBC[t * 32 + 16 + s];
                float Cv = sBC[t * 32 + 24 + s];
                h[s] = __expf(dtv * Aa[s]) * h[s] + dbx * Bv;
                y = fmaf(h[s], Cv, y);
            }
            y = fmaf(Dv, xsv, y);
            sB[t * LDA + d] = y * silu_f(zv);
        }
    }
    __syncthreads();

    // ---- phase 7: out = y @ W_out^T -> sC ----
    gemm64x256(g_WoutT, 256, 0, sB, sC, sW, tid);
    __syncthreads();

    // ---- phase 8: window-reverse scatter store ----
#pragma unroll 4
    for (int i = 0; i < 64; i++) {
        int idx = tid + 256 * i;
        int ix = idx & 7;
        int e = (idx >> 3) & 255;
        int iy = idx >> 11;
        int t = iy * 8 + ix;
        int h = (wy * 8 + iy + SHIFT) & 127;
        int w = (wx * 8 + ix + SHIFT) & 127;
        out[(((b * 256 + e) << 7) + h) * 128 + w] = sC[t * LDA + e];
    }
}

extern "C" void kernel_launch(void* const* d_in, const int* in_sizes, int n_in,
                              void* d_out, int out_size) {
    const float* x = (const float*)d_in[0];
    const float* ln_g = (const float*)d_in[1];
    const float* ln_b = (const float*)d_in[2];
    const float* W_in = (const float*)d_in[3];
    const float* conv_w = (const float*)d_in[4];
    const float* conv_b = (const float*)d_in[5];
    const float* W_xproj = (const float*)d_in[6];
    const float* W_dt = (const float*)d_in[7];
    const float* b_dt = (const float*)d_in[8];
    const float* A_log = (const float*)d_in[9];
    const float* D_param = (const float*)d_in[10];
    const float* W_out = (const float*)d_in[11];
    float* out = (float*)d_out;

    prep_transpose_kernel<<<256, 256>>>(W_in, W_xproj, W_dt, W_out);

    cudaFuncSetAttribute(swin_mamba_kernel,
                         cudaFuncAttributeMaxDynamicSharedMemorySize, SMEM_BYTES);
    swin_mamba_kernel<<<NWIN, 256, SMEM_BYTES>>>(x, ln_g, ln_b, conv_w, conv_b,
                                                 b_dt, A_log, D_param, out);
}

// round 2
// speedup vs baseline: 1.0039x; 1.0039x over previous
#include <cuda_runtime.h>
#include <cstdint>

#define WS      8
#define SHIFT   4
#define NDIM    256
#define DSTATE  8
#define DCONV   4
#define DINNER  256
#define DTRANK  16
#define LTOK    64          // WS*WS tokens per window
#define NWIN    1024        // 4 * 16 * 16 windows
#define LDA     264         // padded row stride (floats) for 64x256 smem buffers

// -------- transposed weight scratch (device globals; no allocation) --------
__device__ float g_WinT[256 * 512];   // [d][e]  e in [0,512)
__device__ float g_WoutT[256 * 256];  // [d][e]
__device__ float g_WxT[256 * 32];     // [d][e]  e in [0,32)
__device__ float g_WdtT[16 * 256];    // [r][d]

__global__ void prep_transpose_kernel(const float* __restrict__ W_in,
                                      const float* __restrict__ W_xproj,
                                      const float* __restrict__ W_dt,
                                      const float* __restrict__ W_out) {
    int idx = blockIdx.x * blockDim.x + threadIdx.x;
    int stride = gridDim.x * blockDim.x;
    for (int i = idx; i < 512 * 256; i += stride) {
        int e = i / 256, d = i % 256;
        g_WinT[d * 512 + e] = W_in[i];
    }
    for (int i = idx; i < 256 * 256; i += stride) {
        int e = i / 256, d = i % 256;
        g_WoutT[d * 256 + e] = W_out[i];
    }
    for (int i = idx; i < 32 * 256; i += stride) {
        int e = i / 256, d = i % 256;
        g_WxT[d * 32 + e] = W_xproj[i];
    }
    for (int i = idx; i < 256 * 16; i += stride) {
        int d = i / 16, r = i % 16;
        g_WdtT[r * 256 + d] = W_dt[i];
    }
}

// -------- packed f32x2 helpers --------
__device__ __forceinline__ unsigned long long pack2(float lo, float hi) {
    unsigned long long r;
    asm("mov.b64 %0, {%1, %2};" : "=l"(r) : "f"(lo), "f"(hi));
    return r;
}
__device__ __forceinline__ void unpack2(unsigned long long v, float& lo, float& hi) {
    asm("mov.b64 {%0, %1}, %2;" : "=f"(lo), "=f"(hi) : "l"(v));
}
__device__ __forceinline__ void fma2(unsigned long long& d, unsigned long long a,
                                     unsigned long long b) {
    asm("fma.rn.f32x2 %0, %1, %2, %0;" : "+l"(d) : "l"(a), "l"(b));
}

// 64x256 <- (64x256) @ WtT(256 x ldw)[:, ecol0:ecol0+256], smem-staged weight chunks.
// Thread (ty,tx) computes 8t x 8e tile via f32x2 pairs over t.
__device__ void gemm64x256(const float* __restrict__ Wt, int ldw, int ecol0,
                           const float* sIn, float* sOut, float* sW, int tid) {
    const int tx = tid & 31, ty = tid >> 5;
    const int tb = ty * 8;
    unsigned long long acc[4][8];
#pragma unroll
    for (int p = 0; p < 4; p++)
#pragma unroll
        for (int jj = 0; jj < 8; jj++) acc[p][jj] = 0ull;

    float pre[8];
#pragma unroll
    for (int i = 0; i < 8; i++) pre[i] = Wt[i * ldw + ecol0 + tid];

    for (int k0 = 0; k0 < 256; k0 += 8) {
        __syncthreads();  // previous chunk's readers done with sW
#pragma unroll
        for (int i = 0; i < 8; i++) sW[i * 256 + tid] = pre[i];
        __syncthreads();
        if (k0 + 8 < 256) {
#pragma unroll
            for (int i = 0; i < 8; i++) pre[i] = Wt[(k0 + 8 + i) * ldw + ecol0 + tid];
        }
#pragma unroll
        for (int j = 0; j < 8; j++) {
            unsigned long long a[4];
#pragma unroll
            for (int p = 0; p < 4; p++)
                a[p] = pack2(sIn[(tb + 2 * p) * LDA + k0 + j],
                             sIn[(tb + 2 * p + 1) * LDA + k0 + j]);
#pragma unroll
            for (int jj = 0; jj < 8; jj++) {
                float w = sW[j * 256 + tx + 32 * jj];
                unsigned long long b = pack2(w, w);
#pragma unroll
                for (int p = 0; p < 4; p++) fma2(acc[p][jj], a[p], b);
            }
        }
    }
#pragma unroll
    for (int p = 0; p < 4; p++)
#pragma unroll
        for (int jj = 0; jj < 8; jj++) {
            float lo, hi;
            unpack2(acc[p][jj], lo, hi);
            sOut[(tb + 2 * p) * LDA + tx + 32 * jj] = lo;
            sOut[(tb + 2 * p + 1) * LDA + tx + 32 * jj] = hi;
        }
}

__device__ __forceinline__ float silu_f(float v) {
    return v / (1.0f + __expf(-v));
}

// smem: sA(64xLDA) | sB(64xLDA) | sC(64xLDA) | sW(8x256) | sBC(64x32)
#define SMEM_FLOATS (3 * LTOK * LDA + 8 * 256 + LTOK * 32)
#define SMEM_BYTES (SMEM_FLOATS * 4)

__global__ __launch_bounds__(256, 1) void swin_mamba_kernel(
    const float* __restrict__ x, const float* __restrict__ ln_g,
    const float* __restrict__ ln_b, const float* __restrict__ conv_w,
    const float* __restrict__ conv_b, const float* __restrict__ b_dt,
    const float* __restrict__ A_log, const float* __restrict__ D_param,
    float* __restrict__ out) {
    extern __shared__ float smem[];
    float* sA = smem;                 // xn -> dt_full
    float* sB = sA + LTOK * LDA;      // raw x -> xc -> xs -> y
    float* sC = sB + LTOK * LDA;      // z -> final out tile
    float* sW = sC + LTOK * LDA;      // weight staging [8][256]
    float* sBC = sW + 8 * 256;        // x_dbl [64][32]

    const int tid = threadIdx.x;
    const int n = blockIdx.x;
    const int b = n >> 8;
    const int rem = n & 255;
    const int wy = rem >> 4;
    const int wx = rem & 15;

    // ---- phase 0: gather rolled window into sB [t][c] (stride LDA) ----
#pragma unroll 4
    for (int i = 0; i < 64; i++) {
        int idx = tid + 256 * i;
        int ix = idx & 7;
        int c = (idx >> 3) & 255;
        int iy = idx >> 11;
        int t = iy * 8 + ix;
        int h = (wy * 8 + iy + SHIFT) & 127;
        int w = (wx * 8 + ix + SHIFT) & 127;
        sB[t * LDA + c] = x[(((b * 256 + c) << 7) + h) * 128 + w];
    }
    __syncthreads();

    // ---- phase 1: LayerNorm over c -> sA (warp per token) ----
    {
        const int wid = tid >> 5, lane = tid & 31;
        for (int t = wid; t < 64; t += 8) {
            float v[8], s = 0.f, s2 = 0.f;
#pragma unroll
            for (int j = 0; j < 8; j++) {
                v[j] = sB[t * LDA + lane + 32 * j];
                s += v[j];
                s2 += v[j] * v[j];
            }
#pragma unroll
            for (int o = 16; o > 0; o >>= 1) {
                s += __shfl_xor_sync(0xffffffffu, s, o);
                s2 += __shfl_xor_sync(0xffffffffu, s2, o);
            }
            float mu = s * (1.0f / 256.0f);
            float var = s2 * (1.0f / 256.0f) - mu * mu;
            float rstd = rsqrtf(var + 1e-5f);
#pragma unroll
            for (int j = 0; j < 8; j++) {
                int c = lane + 32 * j;
                sA[t * LDA + c] = (v[j] - mu) * rstd * ln_g[c] + ln_b[c];
            }
        }
    }
    __syncthreads();

    // ---- phase 2: xz = xn @ W_in^T : xc -> sB, z -> sC ----
    gemm64x256(g_WinT, 512, 0, sA, sB, sW, tid);
    __syncthreads();
    gemm64x256(g_WinT, 512, 256, sA, sC, sW, tid);
    __syncthreads();

    // ---- phase 3: depthwise causal conv + SiLU, in place in sB ----
    {
        const int d = tid;
        float w0 = conv_w[d * 4 + 0], w1 = conv_w[d * 4 + 1];
        float w2 = conv_w[d * 4 + 2], w3 = conv_w[d * 4 + 3];
        float cb = conv_b[d];
        float q0 = 0.f, q1 = 0.f, q2 = 0.f;
#pragma unroll 4
        for (int t = 0; t < 64; t++) {
            float q3 = sB[t * LDA + d];
            float v = cb + w0 * q0 + w1 * q1 + w2 * q2 + w3 * q3;
            sB[t * LDA + d] = silu_f(v);
            q0 = q1; q1 = q2; q2 = q3;
        }
    }
    __syncthreads();

    // ---- phase 4: x_dbl = xs @ W_xproj^T -> sBC [64][32] ----
    {
        const int tx = tid & 31, ty = tid >> 5, tb = ty * 8;
        float acc2[8];
#pragma unroll
        for (int i = 0; i < 8; i++) acc2[i] = 0.f;
#pragma unroll 4
        for (int k = 0; k < 256; k += 4) {
            float wv0 = g_WxT[(k + 0) * 32 + tx];
            float wv1 = g_WxT[(k + 1) * 32 + tx];
            float wv2 = g_WxT[(k + 2) * 32 + tx];
            float wv3 = g_WxT[(k + 3) * 32 + tx];
#pragma unroll
            for (int i = 0; i < 8; i++) {
                const float4 xv = *(const float4*)&sB[(tb + i) * LDA + k];
                acc2[i] = fmaf(xv.x, wv0, acc2[i]);
                acc2[i] = fmaf(xv.y, wv1, acc2[i]);
                acc2[i] = fmaf(xv.z, wv2, acc2[i]);
                acc2[i] = fmaf(xv.w, wv3, acc2[i]);
            }
        }
#pragma unroll
        for (int i = 0; i < 8; i++) sBC[(tb + i) * 32 + tx] = acc2[i];
    }
    __syncthreads();

    // ---- phase 5: dt_full = softplus(dt_raw @ W_dt^T + b_dt) -> sA ----
    {
        const int tx = tid & 31, ty = tid >> 5, tb = ty * 8;
        float acc3[8][8];
#pragma unroll
        for (int i = 0; i < 8; i++)
#pragma unroll
            for (int jj = 0; jj < 8; jj++) acc3[i][jj] = 0.f;
#pragma unroll
        for (int r = 0; r < 16; r++) {
            float wv[8];
#pragma unroll
            for (int jj = 0; jj < 8; jj++) wv[jj] = g_WdtT[r * 256 + tx + 32 * jj];
#pragma unroll
            for (int i = 0; i < 8; i++) {
                float dv = sBC[(tb + i) * 32 + r];
#pragma unroll
                for (int jj = 0; jj < 8; jj++)
                    acc3[i][jj] = fmaf(dv, wv[jj], acc3[i][jj]);
            }
        }
#pragma unroll
        for (int jj = 0; jj < 8; jj++) {
            float bb = b_dt[tx + 32 * jj];
#pragma unroll
            for (int i = 0; i < 8; i++) {
                float v = acc3[i][jj] + bb;
                v = (v > 20.0f) ? v : log1pf(__expf(v));
                sA[(tb + i) * LDA + tx + 32 * jj] = v;
            }
        }
    }
    __syncthreads();

    // ---- phase 6: selective scan + D skip + z gate, y -> sB ----
    {
        const int d = tid;
        float Aa[8];
#pragma unroll
        for (int s = 0; s < 8; s++) Aa[s] = -__expf(A_log[d * 8 + s]);
        float Dv = D_param[d];
        float h[8];
#pragma unroll
        for (int s = 0; s < 8; s++) h[s] = 0.f;
        for (int t = 0; t < 64; t++) {
            float dtv = sA[t * LDA + d];
            float xsv = sB[t * LDA + d];
            float zv = sC[t * LDA + d];
            float dbx = dtv * xsv;
            float y = 0.f;
#pragma unroll
            for (int s = 0; s < 8; s++) {
                float Bv = sBC[t * 32 + 16 + s];
                float Cv = sBC[t * 32 + 24 + s];
                h[s] = __expf(dtv * Aa[s]) * h[s] + dbx * Bv;
                y = fmaf(h[s], Cv, y);
            }
            y = fmaf(Dv, xsv, y);
            sB[t * LDA + d] = y * silu_f(zv);
        }
    }
    __syncthreads();

    // ---- phase 7: out = y @ W_out^T -> sC ----
    gemm64x256(g_WoutT, 256, 0, sB, sC, sW, tid);
    __syncthreads();

    // ---- phase 8: window-reverse scatter store ----
#pragma unroll 4
    for (int i = 0; i < 64; i++) {
        int idx = tid + 256 * i;
        int ix = idx & 7;
        int e = (idx >> 3) & 255;
        int iy = idx >> 11;
        int t = iy * 8 + ix;
        int h = (wy * 8 + iy + SHIFT) & 127;
        int w = (wx * 8 + ix + SHIFT) & 127;
        out[(((b * 256 + e) << 7) + h) * 128 + w] = sC[t * LDA + e];
    }
}

extern "C" void kernel_launch(void* const* d_in, const int* in_sizes, int n_in,
                              void* d_out, int out_size) {
    const float* x = (const float*)d_in[0];
    const float* ln_g = (const float*)d_in[1];
    const float* ln_b = (const float*)d_in[2];
    const float* W_in = (const float*)d_in[3];
    const float* conv_w = (const float*)d_in[4];
    const float* conv_b = (const float*)d_in[5];
    const float* W_xproj = (const float*)d_in[6];
    const float* W_dt = (const float*)d_in[7];
    const float* b_dt = (const float*)d_in[8];
    const float* A_log = (const float*)d_in[9];
    const float* D_param = (const float*)d_in[10];
    const float* W_out = (const float*)d_in[11];
    float* out = (float*)d_out;

    prep_transpose_kernel<<<256, 256>>>(W_in, W_xproj, W_dt, W_out);

    cudaFuncSetAttribute(swin_mamba_kernel,
                         cudaFuncAttributeMaxDynamicSharedMemorySize, SMEM_BYTES);
    swin_mamba_kernel<<<NWIN, 256, SMEM_BYTES>>>(x, ln_g, ln_b, conv_w, conv_b,
                                                 b_dt, A_log, D_param, out);
}